// round 1
// baseline (speedup 1.0000x reference)
#include <cuda_runtime.h>
#include <cuda_bf16.h>
#include <math.h>

// Problem constants
#define D_MODEL 1024
#define D_INNER 2048
#define D_STATE 16
#define DT_RANK 64
#define D_CONV  4
#define BB      2
#define LL      1024
#define BL      (BB * LL)          // 2048 rows
#define XPROJ_N (DT_RANK + 2 * D_STATE)  // 96

// ---------------------------------------------------------------------------
// Device scratch (no cudaMalloc allowed)
// ---------------------------------------------------------------------------
__device__ float g_xz[BB * LL * 2 * D_INNER];     // (2,1024,4096)  33.5 MB
__device__ float g_xc[BB * LL * D_INNER];         // (2,1024,2048)  16.8 MB
__device__ float g_xdbl[BB * LL * XPROJ_N];       // (2,1024,96)
__device__ float g_delta[BB * LL * D_INNER];      // softplus'd delta
__device__ float g_y[BB * LL * D_INNER];          // pre-out_proj activations

// ---------------------------------------------------------------------------
// Generic NT SGEMM: C[M,N] = A[M,K] (lda) * W[N,K]^T, row-major everything.
// 128x128 block tile, BK=8, 256 threads, 8x8 per-thread microtile.
// EPI==1: add bias[n] then softplus.
// Assumes M % 128 == 0, K % 8 == 0 (true for all call sites). N guarded.
// ---------------------------------------------------------------------------
template<int EPI>
__global__ void __launch_bounds__(256, 2)
sgemm_nt(const float* __restrict__ A, const float* __restrict__ W,
         float* __restrict__ C, int M, int N, int K, int lda,
         const float* __restrict__ bias)
{
    __shared__ __align__(16) float As[8][128];
    __shared__ __align__(16) float Bs[8][128];

    const int tid  = threadIdx.x;
    const int tx   = tid & 15;        // 0..15 -> n
    const int ty   = tid >> 4;        // 0..15 -> m
    const int aRow = tid >> 1;        // 0..127
    const int aCol = (tid & 1) << 2;  // 0 or 4

    const long mBase = (long)blockIdx.y * 128;
    const int  nBase = blockIdx.x * 128;

    const float* Aptr = A + (mBase + aRow) * (long)lda + aCol;
    const int    nRow = nBase + aRow;
    const bool   wVal = (nRow < N);
    const float* Wptr = W + (long)nRow * K + aCol;

    float acc[8][8];
#pragma unroll
    for (int i = 0; i < 8; i++)
#pragma unroll
        for (int j = 0; j < 8; j++) acc[i][j] = 0.f;

    for (int k0 = 0; k0 < K; k0 += 8) {
        float4 av = *(const float4*)(Aptr + k0);
        float4 bv = wVal ? *(const float4*)(Wptr + k0)
                         : make_float4(0.f, 0.f, 0.f, 0.f);
        As[aCol + 0][aRow] = av.x;
        As[aCol + 1][aRow] = av.y;
        As[aCol + 2][aRow] = av.z;
        As[aCol + 3][aRow] = av.w;
        Bs[aCol + 0][aRow] = bv.x;
        Bs[aCol + 1][aRow] = bv.y;
        Bs[aCol + 2][aRow] = bv.z;
        Bs[aCol + 3][aRow] = bv.w;
        __syncthreads();

#pragma unroll
        for (int kk = 0; kk < 8; kk++) {
            float4 a0 = *(const float4*)&As[kk][ty * 8];
            float4 a1 = *(const float4*)&As[kk][ty * 8 + 4];
            float4 b0 = *(const float4*)&Bs[kk][tx * 8];
            float4 b1 = *(const float4*)&Bs[kk][tx * 8 + 4];
            float ar[8] = {a0.x, a0.y, a0.z, a0.w, a1.x, a1.y, a1.z, a1.w};
            float br[8] = {b0.x, b0.y, b0.z, b0.w, b1.x, b1.y, b1.z, b1.w};
#pragma unroll
            for (int i = 0; i < 8; i++)
#pragma unroll
                for (int j = 0; j < 8; j++)
                    acc[i][j] = fmaf(ar[i], br[j], acc[i][j]);
        }
        __syncthreads();
    }

#pragma unroll
    for (int i = 0; i < 8; i++) {
        const long row = mBase + ty * 8 + i;
#pragma unroll
        for (int j = 0; j < 8; j++) {
            const int col = nBase + tx * 8 + j;
            if (col < N) {
                float v = acc[i][j];
                if (EPI == 1) {
                    v += bias[col];
                    v = (v > 20.f) ? v : log1pf(expf(v));  // softplus
                }
                C[row * (long)N + col] = v;
            }
        }
    }
}

// ---------------------------------------------------------------------------
// Depthwise causal conv (k=4) + bias + SiLU. Reads xi = xz[..., :D_INNER].
// One thread per (b,l,d) element.
// ---------------------------------------------------------------------------
__global__ void conv_silu_kernel(const float* __restrict__ xz,
                                 const float* __restrict__ cw,
                                 const float* __restrict__ cb,
                                 float* __restrict__ xc)
{
    const int idx = blockIdx.x * blockDim.x + threadIdx.x;
    if (idx >= BB * LL * D_INNER) return;
    const int d = idx & (D_INNER - 1);
    const int r = idx >> 11;
    const int l = r & (LL - 1);
    const int b = r >> 10;

    float acc = cb[d];
#pragma unroll
    for (int i = 0; i < D_CONV; i++) {
        const int ll = l - (D_CONV - 1) + i;
        if (ll >= 0)
            acc = fmaf(xz[((long)(b * LL + ll)) * (2 * D_INNER) + d],
                       cw[d * D_CONV + i], acc);
    }
    // SiLU
    const float s = acc / (1.f + expf(-acc));
    xc[idx] = s;
}

// ---------------------------------------------------------------------------
// Selective scan, fused with D-skip and SiLU(z) gating.
// 16 lanes per channel (one per state), segmented shfl reduction.
// delta already softplus'd (fused into dt_proj epilogue).
// ---------------------------------------------------------------------------
__global__ void scan_kernel(const float* __restrict__ delta,
                            const float* __restrict__ xdbl,
                            const float* __restrict__ xc,
                            const float* __restrict__ xz,
                            const float* __restrict__ A_log,
                            const float* __restrict__ Dv,
                            float* __restrict__ y)
{
    const int t    = blockIdx.x * blockDim.x + threadIdx.x;  // 65536 total
    const int lane = t & 15;                                 // state index n
    const int g    = t >> 4;
    const int d    = g & (D_INNER - 1);
    const int b    = g >> 11;

    const float Aval = -expf(A_log[d * D_STATE + lane]);
    const float Dd   = Dv[d];

    const float* dp  = delta + ((long)b << 21) + d;                 // stride 2048
    const float* xcp = xc    + ((long)b << 21) + d;
    const float* xdp = xdbl  + (long)b * LL * XPROJ_N;
    const float* zp  = xz    + ((long)b << 22) + D_INNER + d;       // stride 4096
    float*       yp  = y     + ((long)b << 21) + d;

    float h = 0.f;
    for (int l = 0; l < LL; l++) {
        const float dl  = dp[(long)l << 11];
        const float xcv = xcp[(long)l << 11];
        const float Bv  = xdp[l * XPROJ_N + DT_RANK + lane];
        const float Cv  = xdp[l * XPROJ_N + DT_RANK + D_STATE + lane];

        const float dA = expf(dl * Aval);
        h = fmaf(dA, h, dl * Bv * xcv);

        float p = h * Cv;
        p += __shfl_xor_sync(0xffffffffu, p, 8);
        p += __shfl_xor_sync(0xffffffffu, p, 4);
        p += __shfl_xor_sync(0xffffffffu, p, 2);
        p += __shfl_xor_sync(0xffffffffu, p, 1);

        if (lane == 0) {
            const float zv  = zp[(long)l << 12];
            const float sig = 1.f / (1.f + expf(-zv));
            yp[(long)l << 11] = (p + xcv * Dd) * (zv * sig);
        }
    }
}

// ---------------------------------------------------------------------------
// Launch
// ---------------------------------------------------------------------------
extern "C" void kernel_launch(void* const* d_in, const int* in_sizes, int n_in,
                              void* d_out, int out_size)
{
    const float* x         = (const float*)d_in[0];
    const float* in_proj_w = (const float*)d_in[1];
    const float* conv_w    = (const float*)d_in[2];
    const float* conv_b    = (const float*)d_in[3];
    const float* x_proj_w  = (const float*)d_in[4];
    const float* dt_proj_w = (const float*)d_in[5];
    const float* dt_proj_b = (const float*)d_in[6];
    const float* A_log     = (const float*)d_in[7];
    const float* Dv        = (const float*)d_in[8];
    const float* out_proj  = (const float*)d_in[9];
    float* out = (float*)d_out;

    float *xz, *xc, *xdbl, *delta, *y;
    cudaGetSymbolAddress((void**)&xz,    g_xz);
    cudaGetSymbolAddress((void**)&xc,    g_xc);
    cudaGetSymbolAddress((void**)&xdbl,  g_xdbl);
    cudaGetSymbolAddress((void**)&delta, g_delta);
    cudaGetSymbolAddress((void**)&y,     g_y);

    // 1. xz = x @ in_proj_w.T   (M=2048, N=4096, K=1024)
    sgemm_nt<0><<<dim3(2 * D_INNER / 128, BL / 128), 256>>>(
        x, in_proj_w, xz, BL, 2 * D_INNER, D_MODEL, D_MODEL, nullptr);

    // 2. xc = silu(causal_conv(xi) + b)
    conv_silu_kernel<<<(BB * LL * D_INNER + 255) / 256, 256>>>(
        xz, conv_w, conv_b, xc);

    // 3. x_dbl = xc @ x_proj_w.T  (M=2048, N=96, K=2048)
    sgemm_nt<0><<<dim3(1, BL / 128), 256>>>(
        xc, x_proj_w, xdbl, BL, XPROJ_N, D_INNER, D_INNER, nullptr);

    // 4. delta = softplus(dt @ dt_proj_w.T + b)  (M=2048, N=2048, K=64, lda=96)
    sgemm_nt<1><<<dim3(D_INNER / 128, BL / 128), 256>>>(
        xdbl, dt_proj_w, delta, BL, D_INNER, DT_RANK, XPROJ_N, dt_proj_b);

    // 5. selective scan + D skip + SiLU(z) gating
    scan_kernel<<<(BB * D_INNER * D_STATE) / 256, 256>>>(
        delta, xdbl, xc, xz, A_log, Dv, y);

    // 6. out = y @ out_proj_w.T  (M=2048, N=1024, K=2048)
    sgemm_nt<0><<<dim3(D_MODEL / 128, BL / 128), 256>>>(
        y, out_proj, out, BL, D_MODEL, D_INNER, D_INNER, nullptr);
}

// round 2
// speedup vs baseline: 1.1529x; 1.1529x over previous
#include <cuda_runtime.h>
#include <cuda_bf16.h>
#include <math.h>

// Problem constants
#define D_MODEL 1024
#define D_INNER 2048
#define D_STATE 16
#define DT_RANK 64
#define D_CONV  4
#define BB      2
#define LL      1024
#define BL      (BB * LL)                 // 2048 rows
#define XPROJ_N (DT_RANK + 2 * D_STATE)   // 96

// ---------------------------------------------------------------------------
// Device scratch (no cudaMalloc allowed)
// ---------------------------------------------------------------------------
__device__ float g_xz[BB * LL * 2 * D_INNER];
__device__ float g_xc[BB * LL * D_INNER];
__device__ float g_xdbl[BB * LL * XPROJ_N];
__device__ float g_delta[BB * LL * D_INNER];
__device__ float g_y[BB * LL * D_INNER];

// ---------------------------------------------------------------------------
// Helpers: tf32 conversion, cp.async, mma
// ---------------------------------------------------------------------------
__device__ __forceinline__ unsigned f2tf32(float x) {
    unsigned r;
    asm("cvt.rna.tf32.f32 %0, %1;" : "=r"(r) : "f"(x));
    return r;
}

__device__ __forceinline__ void cp_async16(void* smem, const void* gptr) {
    unsigned s = (unsigned)__cvta_generic_to_shared(smem);
    asm volatile("cp.async.cg.shared.global [%0], [%1], 16;" :: "r"(s), "l"(gptr));
}
__device__ __forceinline__ void cp_commit() {
    asm volatile("cp.async.commit_group;");
}
__device__ __forceinline__ void cp_wait1() {
    asm volatile("cp.async.wait_group 1;" ::: "memory");
}
__device__ __forceinline__ void cp_wait0() {
    asm volatile("cp.async.wait_group 0;" ::: "memory");
}

__device__ __forceinline__ void mma_tf32(float (&c)[4],
                                         unsigned a0, unsigned a1, unsigned a2, unsigned a3,
                                         unsigned b0, unsigned b1) {
    asm volatile(
        "mma.sync.aligned.m16n8k8.row.col.f32.tf32.tf32.f32 "
        "{%0,%1,%2,%3},{%4,%5,%6,%7},{%8,%9},{%0,%1,%2,%3};"
        : "+f"(c[0]), "+f"(c[1]), "+f"(c[2]), "+f"(c[3])
        : "r"(a0), "r"(a1), "r"(a2), "r"(a3), "r"(b0), "r"(b1));
}

// ---------------------------------------------------------------------------
// TF32 tensor-core GEMM: C[M,N] = A[M,K](lda) * W[N,K]^T (ldw=K), row-major.
// BM=BN=128, BK=16, 512 threads = 16 warps in a 4x4 grid, warp tile 32x32.
// SPLIT3==1 : 3xTF32 error-compensated path (~fp32 accuracy)
// SPLIT3==0 : single TF32
// EPI==1    : +bias, softplus
// Requires M%128==0, N%128==0, K%16==0 (all call sites satisfy this).
// ---------------------------------------------------------------------------
#define BM 128
#define BN 128
#define BKT 16
#define BKP 20   // padded smem stride (floats) -> conflict-free

template<int SPLIT3, int EPI>
__global__ void __launch_bounds__(512, 1)
tf32_gemm(const float* __restrict__ A, const float* __restrict__ W,
          float* __restrict__ C, int M, int N, int K, int lda,
          const float* __restrict__ bias)
{
    __shared__ float As[2][BM][BKP];
    __shared__ float Ws[2][BN][BKP];

    const int tid  = threadIdx.x;
    const int wid  = tid >> 5;
    const int lane = tid & 31;
    const int lr   = lane >> 2;   // 0..7
    const int lc   = lane & 3;    // 0..3

    const int wm = wid >> 2;      // 0..3
    const int wn = wid & 3;       // 0..3
    const int wmBase = wm * 32;
    const int wnBase = wn * 32;

    const long blockM = (long)blockIdx.y * BM;
    const int  blockN = blockIdx.x * BN;

    // global load mapping: each thread copies one float4 per tile per array
    const int gRow = tid >> 2;          // 0..127
    const int gCol = (tid & 3) << 2;    // 0,4,8,12
    const float* Ag = A + (blockM + gRow) * (long)lda + gCol;
    const float* Wg = W + (long)(blockN + gRow) * K + gCol;

    float acc[2][4][4];
#pragma unroll
    for (int mi = 0; mi < 2; mi++)
#pragma unroll
        for (int ni = 0; ni < 4; ni++)
#pragma unroll
            for (int j = 0; j < 4; j++) acc[mi][ni][j] = 0.f;

    const int T = K / BKT;

    // prologue: tile 0 -> buf 0
    cp_async16(&As[0][gRow][gCol], Ag);
    cp_async16(&Ws[0][gRow][gCol], Wg);
    cp_commit();

    int buf = 0;
    for (int t = 0; t < T; t++) {
        if (t + 1 < T) {
            const int koff = (t + 1) * BKT;
            cp_async16(&As[buf ^ 1][gRow][gCol], Ag + koff);
            cp_async16(&Ws[buf ^ 1][gRow][gCol], Wg + koff);
            cp_commit();
            cp_wait1();
        } else {
            cp_wait0();
        }
        __syncthreads();

#pragma unroll
        for (int kk = 0; kk < 2; kk++) {
            const int k0 = kk * 8;
            unsigned ahi[2][4], alo[2][4];
#pragma unroll
            for (int mi = 0; mi < 2; mi++) {
                const int r0 = wmBase + mi * 16 + lr;
                float a0 = As[buf][r0][k0 + lc];
                float a1 = As[buf][r0 + 8][k0 + lc];
                float a2 = As[buf][r0][k0 + lc + 4];
                float a3 = As[buf][r0 + 8][k0 + lc + 4];
                ahi[mi][0] = f2tf32(a0);
                ahi[mi][1] = f2tf32(a1);
                ahi[mi][2] = f2tf32(a2);
                ahi[mi][3] = f2tf32(a3);
                if (SPLIT3) {
                    alo[mi][0] = f2tf32(a0 - __uint_as_float(ahi[mi][0]));
                    alo[mi][1] = f2tf32(a1 - __uint_as_float(ahi[mi][1]));
                    alo[mi][2] = f2tf32(a2 - __uint_as_float(ahi[mi][2]));
                    alo[mi][3] = f2tf32(a3 - __uint_as_float(ahi[mi][3]));
                }
            }
            unsigned bhi[4][2], blo[4][2];
#pragma unroll
            for (int ni = 0; ni < 4; ni++) {
                const int c0 = wnBase + ni * 8 + lr;
                float b0 = Ws[buf][c0][k0 + lc];
                float b1 = Ws[buf][c0][k0 + lc + 4];
                bhi[ni][0] = f2tf32(b0);
                bhi[ni][1] = f2tf32(b1);
                if (SPLIT3) {
                    blo[ni][0] = f2tf32(b0 - __uint_as_float(bhi[ni][0]));
                    blo[ni][1] = f2tf32(b1 - __uint_as_float(bhi[ni][1]));
                }
            }
#pragma unroll
            for (int mi = 0; mi < 2; mi++)
#pragma unroll
                for (int ni = 0; ni < 4; ni++) {
                    if (SPLIT3) {
                        mma_tf32(acc[mi][ni],
                                 alo[mi][0], alo[mi][1], alo[mi][2], alo[mi][3],
                                 bhi[ni][0], bhi[ni][1]);
                        mma_tf32(acc[mi][ni],
                                 ahi[mi][0], ahi[mi][1], ahi[mi][2], ahi[mi][3],
                                 blo[ni][0], blo[ni][1]);
                    }
                    mma_tf32(acc[mi][ni],
                             ahi[mi][0], ahi[mi][1], ahi[mi][2], ahi[mi][3],
                             bhi[ni][0], bhi[ni][1]);
                }
        }
        __syncthreads();
        buf ^= 1;
    }

    // epilogue
#pragma unroll
    for (int mi = 0; mi < 2; mi++) {
#pragma unroll
        for (int ni = 0; ni < 4; ni++) {
            const int colBase = blockN + wnBase + ni * 8 + 2 * lc;
#pragma unroll
            for (int half = 0; half < 2; half++) {
                const long row = blockM + wmBase + mi * 16 + lr + half * 8;
                float v0 = acc[mi][ni][half * 2 + 0];
                float v1 = acc[mi][ni][half * 2 + 1];
                if (EPI == 1) {
                    v0 += bias[colBase];
                    v1 += bias[colBase + 1];
                    v0 = (v0 > 20.f) ? v0 : log1pf(expf(v0));
                    v1 = (v1 > 20.f) ? v1 : log1pf(expf(v1));
                }
                *(float2*)&C[row * (long)N + colBase] = make_float2(v0, v1);
            }
        }
    }
}

// ---------------------------------------------------------------------------
// SIMT SGEMM (kept only for x_proj, N=96): 128x128 tile, BK=8, 256 threads.
// ---------------------------------------------------------------------------
__global__ void __launch_bounds__(256, 2)
sgemm_nt(const float* __restrict__ A, const float* __restrict__ W,
         float* __restrict__ C, int M, int N, int K, int lda)
{
    __shared__ __align__(16) float As[8][128];
    __shared__ __align__(16) float Bs[8][128];

    const int tid  = threadIdx.x;
    const int tx   = tid & 15;
    const int ty   = tid >> 4;
    const int aRow = tid >> 1;
    const int aCol = (tid & 1) << 2;

    const long mBase = (long)blockIdx.y * 128;
    const int  nBase = blockIdx.x * 128;

    const float* Aptr = A + (mBase + aRow) * (long)lda + aCol;
    const int    nRow = nBase + aRow;
    const bool   wVal = (nRow < N);
    const float* Wptr = W + (long)nRow * K + aCol;

    float acc[8][8];
#pragma unroll
    for (int i = 0; i < 8; i++)
#pragma unroll
        for (int j = 0; j < 8; j++) acc[i][j] = 0.f;

    for (int k0 = 0; k0 < K; k0 += 8) {
        float4 av = *(const float4*)(Aptr + k0);
        float4 bv = wVal ? *(const float4*)(Wptr + k0)
                         : make_float4(0.f, 0.f, 0.f, 0.f);
        As[aCol + 0][aRow] = av.x;
        As[aCol + 1][aRow] = av.y;
        As[aCol + 2][aRow] = av.z;
        As[aCol + 3][aRow] = av.w;
        Bs[aCol + 0][aRow] = bv.x;
        Bs[aCol + 1][aRow] = bv.y;
        Bs[aCol + 2][aRow] = bv.z;
        Bs[aCol + 3][aRow] = bv.w;
        __syncthreads();

#pragma unroll
        for (int kk = 0; kk < 8; kk++) {
            float4 a0 = *(const float4*)&As[kk][ty * 8];
            float4 a1 = *(const float4*)&As[kk][ty * 8 + 4];
            float4 b0 = *(const float4*)&Bs[kk][tx * 8];
            float4 b1 = *(const float4*)&Bs[kk][tx * 8 + 4];
            float ar[8] = {a0.x, a0.y, a0.z, a0.w, a1.x, a1.y, a1.z, a1.w};
            float br[8] = {b0.x, b0.y, b0.z, b0.w, b1.x, b1.y, b1.z, b1.w};
#pragma unroll
            for (int i = 0; i < 8; i++)
#pragma unroll
                for (int j = 0; j < 8; j++)
                    acc[i][j] = fmaf(ar[i], br[j], acc[i][j]);
        }
        __syncthreads();
    }

#pragma unroll
    for (int i = 0; i < 8; i++) {
        const long row = mBase + ty * 8 + i;
#pragma unroll
        for (int j = 0; j < 8; j++) {
            const int col = nBase + tx * 8 + j;
            if (col < N) C[row * (long)N + col] = acc[i][j];
        }
    }
}

// ---------------------------------------------------------------------------
// Depthwise causal conv (k=4) + bias + SiLU
// ---------------------------------------------------------------------------
__global__ void conv_silu_kernel(const float* __restrict__ xz,
                                 const float* __restrict__ cw,
                                 const float* __restrict__ cb,
                                 float* __restrict__ xc)
{
    const int idx = blockIdx.x * blockDim.x + threadIdx.x;
    if (idx >= BB * LL * D_INNER) return;
    const int d = idx & (D_INNER - 1);
    const int r = idx >> 11;
    const int l = r & (LL - 1);
    const int b = r >> 10;

    float acc = cb[d];
#pragma unroll
    for (int i = 0; i < D_CONV; i++) {
        const int ll = l - (D_CONV - 1) + i;
        if (ll >= 0)
            acc = fmaf(xz[((long)(b * LL + ll)) * (2 * D_INNER) + d],
                       cw[d * D_CONV + i], acc);
    }
    const float s = acc / (1.f + expf(-acc));
    xc[idx] = s;
}

// ---------------------------------------------------------------------------
// Selective scan + D skip + SiLU(z) gating
// ---------------------------------------------------------------------------
__global__ void scan_kernel(const float* __restrict__ delta,
                            const float* __restrict__ xdbl,
                            const float* __restrict__ xc,
                            const float* __restrict__ xz,
                            const float* __restrict__ A_log,
                            const float* __restrict__ Dv,
                            float* __restrict__ y)
{
    const int t    = blockIdx.x * blockDim.x + threadIdx.x;
    const int lane = t & 15;
    const int g    = t >> 4;
    const int d    = g & (D_INNER - 1);
    const int b    = g >> 11;

    const float Aval = -expf(A_log[d * D_STATE + lane]);
    const float Dd   = Dv[d];

    const float* dp  = delta + ((long)b << 21) + d;
    const float* xcp = xc    + ((long)b << 21) + d;
    const float* xdp = xdbl  + (long)b * LL * XPROJ_N;
    const float* zp  = xz    + ((long)b << 22) + D_INNER + d;
    float*       yp  = y     + ((long)b << 21) + d;

    float h = 0.f;
    for (int l = 0; l < LL; l++) {
        const float dl  = dp[(long)l << 11];
        const float xcv = xcp[(long)l << 11];
        const float Bv  = xdp[l * XPROJ_N + DT_RANK + lane];
        const float Cv  = xdp[l * XPROJ_N + DT_RANK + D_STATE + lane];

        const float dA = expf(dl * Aval);
        h = fmaf(dA, h, dl * Bv * xcv);

        float p = h * Cv;
        p += __shfl_xor_sync(0xffffffffu, p, 8);
        p += __shfl_xor_sync(0xffffffffu, p, 4);
        p += __shfl_xor_sync(0xffffffffu, p, 2);
        p += __shfl_xor_sync(0xffffffffu, p, 1);

        if (lane == 0) {
            const float zv  = zp[(long)l << 12];
            const float sig = 1.f / (1.f + expf(-zv));
            yp[(long)l << 11] = (p + xcv * Dd) * (zv * sig);
        }
    }
}

// ---------------------------------------------------------------------------
// Launch
// ---------------------------------------------------------------------------
extern "C" void kernel_launch(void* const* d_in, const int* in_sizes, int n_in,
                              void* d_out, int out_size)
{
    const float* x         = (const float*)d_in[0];
    const float* in_proj_w = (const float*)d_in[1];
    const float* conv_w    = (const float*)d_in[2];
    const float* conv_b    = (const float*)d_in[3];
    const float* x_proj_w  = (const float*)d_in[4];
    const float* dt_proj_w = (const float*)d_in[5];
    const float* dt_proj_b = (const float*)d_in[6];
    const float* A_log     = (const float*)d_in[7];
    const float* Dv        = (const float*)d_in[8];
    const float* out_proj  = (const float*)d_in[9];
    float* out = (float*)d_out;

    float *xz, *xc, *xdbl, *delta, *y;
    cudaGetSymbolAddress((void**)&xz,    g_xz);
    cudaGetSymbolAddress((void**)&xc,    g_xc);
    cudaGetSymbolAddress((void**)&xdbl,  g_xdbl);
    cudaGetSymbolAddress((void**)&delta, g_delta);
    cudaGetSymbolAddress((void**)&y,     g_y);

    // 1. xz = x @ in_proj_w.T  (M=2048, N=4096, K=1024)  3xTF32
    tf32_gemm<1, 0><<<dim3(2 * D_INNER / BN, BL / BM), 512>>>(
        x, in_proj_w, xz, BL, 2 * D_INNER, D_MODEL, D_MODEL, nullptr);

    // 2. xc = silu(causal_conv(xi) + b)
    conv_silu_kernel<<<(BB * LL * D_INNER + 255) / 256, 256>>>(
        xz, conv_w, conv_b, xc);

    // 3. x_dbl = xc @ x_proj_w.T  (M=2048, N=96, K=2048)  SIMT
    sgemm_nt<<<dim3(1, BL / 128), 256>>>(
        xc, x_proj_w, xdbl, BL, XPROJ_N, D_INNER, D_INNER);

    // 4. delta = softplus(dt @ dt_proj_w.T + b)  (M=2048, N=2048, K=64, lda=96)  TF32
    tf32_gemm<0, 1><<<dim3(D_INNER / BN, BL / BM), 512>>>(
        xdbl, dt_proj_w, delta, BL, D_INNER, DT_RANK, XPROJ_N, dt_proj_b);

    // 5. selective scan + D skip + SiLU(z) gating
    scan_kernel<<<(BB * D_INNER * D_STATE) / 256, 256>>>(
        delta, xdbl, xc, xz, A_log, Dv, y);

    // 6. out = y @ out_proj_w.T  (M=2048, N=1024, K=2048)  3xTF32
    tf32_gemm<1, 0><<<dim3(D_MODEL / BN, BL / BM), 512>>>(
        y, out_proj, out, BL, D_MODEL, D_INNER, D_INNER, nullptr);
}

// round 4
// speedup vs baseline: 1.5526x; 1.3467x over previous
#include <cuda_runtime.h>
#include <cuda_bf16.h>
#include <math.h>
#include <stdint.h>

// Problem constants
#define D_MODEL 1024
#define D_INNER 2048
#define D_STATE 16
#define DT_RANK 64
#define D_CONV  4
#define BB      2
#define LL      1024
#define BL      (BB * LL)                 // 2048 rows
#define XPROJ_N (DT_RANK + 2 * D_STATE)   // 96
#define KSPLIT  4

// ---------------------------------------------------------------------------
// Device scratch (no cudaMalloc allowed)
// ---------------------------------------------------------------------------
__device__ float g_xz[BL * 2 * D_INNER];
__device__ float g_xc[BL * D_INNER];
__device__ float g_xdbl[BL * XPROJ_N];
__device__ float g_xpart[KSPLIT * BL * XPROJ_N];
__device__ float g_delta[BL * D_INNER];
__device__ float g_y[BL * D_INNER];

// ---------------------------------------------------------------------------
// bf16 helpers
// ---------------------------------------------------------------------------
__device__ __forceinline__ void cvt_pair(float x, float y,
                                         uint32_t& hi, uint32_t& lo) {
    // hi = {bf16(y) , bf16(x)} with x in low half
    asm("cvt.rn.bf16x2.f32 %0, %1, %2;" : "=r"(hi) : "f"(y), "f"(x));
    const float hx = __uint_as_float(hi << 16);
    const float hy = __uint_as_float(hi & 0xFFFF0000u);
    asm("cvt.rn.bf16x2.f32 %0, %1, %2;" : "=r"(lo) : "f"(y - hy), "f"(x - hx));
}

__device__ __forceinline__ void mma_bf16(float (&c)[4],
                                         uint32_t a0, uint32_t a1,
                                         uint32_t a2, uint32_t a3,
                                         uint32_t b0, uint32_t b1) {
    asm volatile(
        "mma.sync.aligned.m16n8k16.row.col.f32.bf16.bf16.f32 "
        "{%0,%1,%2,%3},{%4,%5,%6,%7},{%8,%9},{%0,%1,%2,%3};"
        : "+f"(c[0]), "+f"(c[1]), "+f"(c[2]), "+f"(c[3])
        : "r"(a0), "r"(a1), "r"(a2), "r"(a3), "r"(b0), "r"(b1));
}

// ---------------------------------------------------------------------------
// bf16-split tensor GEMM:  C[M,N] = A[M,K](lda) * W[N,K]^T(ldw), row-major.
// Block tile BM x BN (BM = 32*WMG, BN = 32*WNG), BK = 16.
// Producers convert f32 -> bf16 hi/lo ONCE and store fragment-major, so
// consumers load each mma fragment with a single LDS.128 (uint4).
// 3 MMAs per logical product: hi*hi + hi*lo + lo*hi  (~1e-4 accuracy).
// Register-staged double buffer, one __syncthreads per K-tile.
// EPI==1: +bias then softplus.
// Split-K via blockIdx.z: k-offset z*T*16, C += z*czstride.
// Requires M%BM==0, N%BN==0, K%16==0, 16B-aligned rows.
// ---------------------------------------------------------------------------
template<int WMG, int WNG, int EPI>
__global__ void __launch_bounds__(WMG * WNG * 32)
bf16_gemm(const float* __restrict__ A, const float* __restrict__ W,
          float* __restrict__ C, int lda, int ldw, int ldc, int T,
          long czstride, const float* __restrict__ bias)
{
    constexpr int BM   = WMG * 32;
    constexpr int BN   = WNG * 32;
    constexpr int NTHR = WMG * WNG * 32;
    constexpr int NA   = (BM * 4 + NTHR - 1) / NTHR;   // float4 loads per thread (A)
    constexpr int NB   = (BN * 4 + NTHR - 1) / NTHR;
    constexpr int AHI = 0;
    constexpr int ALO = BM * 8;
    constexpr int BHI = BM * 16;
    constexpr int BLO = BM * 16 + BN * 8;

    __shared__ uint32_t sm[2][(BM + BN) * 16];

    const int tid  = threadIdx.x;
    const int wid  = tid >> 5;
    const int lane = tid & 31;
    const int lr   = lane >> 2;    // 0..7
    const int lc   = lane & 3;     // 0..3
    const int wm   = wid / WNG;    // 0..WMG-1
    const int wn   = wid % WNG;    // 0..WNG-1

    const long blockM = (long)blockIdx.y * BM;
    const long blockN = (long)blockIdx.x * BN;
    const int  koff   = blockIdx.z * T * 16;

    const float* Ab = A + blockM * lda + koff;
    const float* Wb = W + blockN * (long)ldw + koff;

    float acc[2][4][4];
#pragma unroll
    for (int mi = 0; mi < 2; mi++)
#pragma unroll
        for (int ni = 0; ni < 4; ni++)
#pragma unroll
            for (int j = 0; j < 4; j++) acc[mi][ni][j] = 0.f;

    float4 rA[NA], rB[NB];

    // prologue: stage tile 0
#pragma unroll
    for (int i = 0; i < NA; i++) {
        const int s = i * NTHR + tid;
        if (s < BM * 4)
            rA[i] = *(const float4*)(Ab + (s >> 2) * (long)lda + (s & 3) * 4);
    }
#pragma unroll
    for (int i = 0; i < NB; i++) {
        const int s = i * NTHR + tid;
        if (s < BN * 4)
            rB[i] = *(const float4*)(Wb + (s >> 2) * (long)ldw + (s & 3) * 4);
    }

    for (int t = 0; t < T; t++) {
        const int buf = t & 1;
        uint32_t* sb = sm[buf];

        // ---- convert + STS staged tile ----
#pragma unroll
        for (int i = 0; i < NA; i++) {
            const int s = i * NTHR + tid;
            if (s < BM * 4) {
                const int row = s >> 2, q = s & 3;
                uint32_t h0, l0, h1, l1;
                cvt_pair(rA[i].x, rA[i].y, h0, l0);
                cvt_pair(rA[i].z, rA[i].w, h1, l1);
                const int base = (row >> 4) * 128 + (row & 7) * 16 +
                                 (q >> 1) * 2 + ((row >> 3) & 1);
                const int lc0 = (2 * q) & 3;
                sb[AHI + base + lc0 * 4]       = h0;
                sb[AHI + base + (lc0 + 1) * 4] = h1;
                sb[ALO + base + lc0 * 4]       = l0;
                sb[ALO + base + (lc0 + 1) * 4] = l1;
            }
        }
#pragma unroll
        for (int i = 0; i < NB; i++) {
            const int s = i * NTHR + tid;
            if (s < BN * 4) {
                const int n = s >> 2, q = s & 3;
                uint32_t h0, l0, h1, l1;
                cvt_pair(rB[i].x, rB[i].y, h0, l0);
                cvt_pair(rB[i].z, rB[i].w, h1, l1);
                const int base = (n >> 4) * 128 + (n & 7) * 16 +
                                 ((n >> 3) & 1) * 2 + (q >> 1);
                const int lc0 = (2 * q) & 3;
                sb[BHI + base + lc0 * 4]       = h0;
                sb[BHI + base + (lc0 + 1) * 4] = h1;
                sb[BLO + base + lc0 * 4]       = l0;
                sb[BLO + base + (lc0 + 1) * 4] = l1;
            }
        }
        __syncthreads();

        // ---- stage next tile (overlaps with MMAs below) ----
        if (t + 1 < T) {
            const int k1 = (t + 1) * 16;
#pragma unroll
            for (int i = 0; i < NA; i++) {
                const int s = i * NTHR + tid;
                if (s < BM * 4)
                    rA[i] = *(const float4*)(Ab + (s >> 2) * (long)lda + k1 + (s & 3) * 4);
            }
#pragma unroll
            for (int i = 0; i < NB; i++) {
                const int s = i * NTHR + tid;
                if (s < BN * 4)
                    rB[i] = *(const float4*)(Wb + (s >> 2) * (long)ldw + k1 + (s & 3) * 4);
            }
        }

        // ---- consume: vectorized fragment loads + MMAs ----
        uint4 Ah[2], Al[2], Bh[2], Bl[2];
#pragma unroll
        for (int mi = 0; mi < 2; mi++) {
            const int o = (wm * 2 + mi) * 128 + lane * 4;
            Ah[mi] = *(const uint4*)&sb[AHI + o];
            Al[mi] = *(const uint4*)&sb[ALO + o];
        }
#pragma unroll
        for (int np = 0; np < 2; np++) {
            const int o = (wn * 2 + np) * 128 + lane * 4;
            Bh[np] = *(const uint4*)&sb[BHI + o];
            Bl[np] = *(const uint4*)&sb[BLO + o];
        }
#pragma unroll
        for (int mi = 0; mi < 2; mi++)
#pragma unroll
            for (int ni = 0; ni < 4; ni++) {
                const int np = ni >> 1;
                const uint32_t b0h = (ni & 1) ? Bh[np].z : Bh[np].x;
                const uint32_t b1h = (ni & 1) ? Bh[np].w : Bh[np].y;
                const uint32_t b0l = (ni & 1) ? Bl[np].z : Bl[np].x;
                const uint32_t b1l = (ni & 1) ? Bl[np].w : Bl[np].y;
                mma_bf16(acc[mi][ni], Ah[mi].x, Ah[mi].y, Ah[mi].z, Ah[mi].w, b0h, b1h);
                mma_bf16(acc[mi][ni], Ah[mi].x, Ah[mi].y, Ah[mi].z, Ah[mi].w, b0l, b1l);
                mma_bf16(acc[mi][ni], Al[mi].x, Al[mi].y, Al[mi].z, Al[mi].w, b0h, b1h);
            }
        __syncthreads();
    }

    // ---- epilogue ----
    float* Cb = C + (long)blockIdx.z * czstride;
#pragma unroll
    for (int mi = 0; mi < 2; mi++) {
#pragma unroll
        for (int ni = 0; ni < 4; ni++) {
            const int  col = (int)blockN + wn * 32 + ni * 8 + lc * 2;
            const long r0  = blockM + wm * 32 + mi * 16 + lr;
            float v0 = acc[mi][ni][0], v1 = acc[mi][ni][1];
            float v2 = acc[mi][ni][2], v3 = acc[mi][ni][3];
            if (EPI == 1) {
                const float b0 = bias[col], b1 = bias[col + 1];
                v0 += b0; v1 += b1; v2 += b0; v3 += b1;
                v0 = (v0 > 20.f) ? v0 : log1pf(expf(v0));
                v1 = (v1 > 20.f) ? v1 : log1pf(expf(v1));
                v2 = (v2 > 20.f) ? v2 : log1pf(expf(v2));
                v3 = (v3 > 20.f) ? v3 : log1pf(expf(v3));
            }
            *(float2*)&Cb[r0 * ldc + col]       = make_float2(v0, v1);
            *(float2*)&Cb[(r0 + 8) * ldc + col] = make_float2(v2, v3);
        }
    }
}

// ---------------------------------------------------------------------------
// Split-K partial reduction: xdbl = sum_z xpart[z]
// ---------------------------------------------------------------------------
__global__ void reduce_k(const float* __restrict__ p, float* __restrict__ o)
{
    const int n4 = BL * XPROJ_N / 4;
    const int i = blockIdx.x * blockDim.x + threadIdx.x;
    if (i >= n4) return;
    const float4* p4 = (const float4*)p;
    float4 a = p4[i];
    const float4 b = p4[n4 + i];
    const float4 c = p4[2 * n4 + i];
    const float4 d = p4[3 * n4 + i];
    a.x += b.x + c.x + d.x;
    a.y += b.y + c.y + d.y;
    a.z += b.z + c.z + d.z;
    a.w += b.w + c.w + d.w;
    ((float4*)o)[i] = a;
}

// ---------------------------------------------------------------------------
// Depthwise causal conv (k=4) + bias + SiLU
// ---------------------------------------------------------------------------
__global__ void conv_silu_kernel(const float* __restrict__ xz,
                                 const float* __restrict__ cw,
                                 const float* __restrict__ cb,
                                 float* __restrict__ xc)
{
    const int idx = blockIdx.x * blockDim.x + threadIdx.x;
    if (idx >= BB * LL * D_INNER) return;
    const int d = idx & (D_INNER - 1);
    const int r = idx >> 11;
    const int l = r & (LL - 1);
    const int b = r >> 10;

    float acc = cb[d];
#pragma unroll
    for (int i = 0; i < D_CONV; i++) {
        const int ll = l - (D_CONV - 1) + i;
        if (ll >= 0)
            acc = fmaf(xz[((long)(b * LL + ll)) * (2 * D_INNER) + d],
                       cw[d * D_CONV + i], acc);
    }
    const float s = acc / (1.f + expf(-acc));
    xc[idx] = s;
}

// ---------------------------------------------------------------------------
// Selective scan + D skip + SiLU(z) gating
// ---------------------------------------------------------------------------
__global__ void scan_kernel(const float* __restrict__ delta,
                            const float* __restrict__ xdbl,
                            const float* __restrict__ xc,
                            const float* __restrict__ xz,
                            const float* __restrict__ A_log,
                            const float* __restrict__ Dv,
                            float* __restrict__ y)
{
    const int t    = blockIdx.x * blockDim.x + threadIdx.x;
    const int lane = t & 15;
    const int g    = t >> 4;
    const int d    = g & (D_INNER - 1);
    const int b    = g >> 11;

    const float Aval = -expf(A_log[d * D_STATE + lane]);
    const float Dd   = Dv[d];

    const float* dp  = delta + ((long)b << 21) + d;
    const float* xcp = xc    + ((long)b << 21) + d;
    const float* xdp = xdbl  + (long)b * LL * XPROJ_N;
    const float* zp  = xz    + ((long)b << 22) + D_INNER + d;
    float*       yp  = y     + ((long)b << 21) + d;

    float h = 0.f;
    for (int l = 0; l < LL; l++) {
        const float dl  = dp[(long)l << 11];
        const float xcv = xcp[(long)l << 11];
        const float Bv  = xdp[l * XPROJ_N + DT_RANK + lane];
        const float Cv  = xdp[l * XPROJ_N + DT_RANK + D_STATE + lane];

        const float dA = expf(dl * Aval);
        h = fmaf(dA, h, dl * Bv * xcv);

        float p = h * Cv;
        p += __shfl_xor_sync(0xffffffffu, p, 8);
        p += __shfl_xor_sync(0xffffffffu, p, 4);
        p += __shfl_xor_sync(0xffffffffu, p, 2);
        p += __shfl_xor_sync(0xffffffffu, p, 1);

        if (lane == 0) {
            const float zv  = zp[(long)l << 12];
            const float sig = 1.f / (1.f + expf(-zv));
            yp[(long)l << 11] = (p + xcv * Dd) * (zv * sig);
        }
    }
}

// ---------------------------------------------------------------------------
// Launch
// ---------------------------------------------------------------------------
extern "C" void kernel_launch(void* const* d_in, const int* in_sizes, int n_in,
                              void* d_out, int out_size)
{
    const float* x         = (const float*)d_in[0];
    const float* in_proj_w = (const float*)d_in[1];
    const float* conv_w    = (const float*)d_in[2];
    const float* conv_b    = (const float*)d_in[3];
    const float* x_proj_w  = (const float*)d_in[4];
    const float* dt_proj_w = (const float*)d_in[5];
    const float* dt_proj_b = (const float*)d_in[6];
    const float* A_log     = (const float*)d_in[7];
    const float* Dv        = (const float*)d_in[8];
    const float* out_proj  = (const float*)d_in[9];
    float* out = (float*)d_out;

    float *xz, *xc, *xdbl, *xpart, *delta, *y;
    cudaGetSymbolAddress((void**)&xz,    g_xz);
    cudaGetSymbolAddress((void**)&xc,    g_xc);
    cudaGetSymbolAddress((void**)&xdbl,  g_xdbl);
    cudaGetSymbolAddress((void**)&xpart, g_xpart);
    cudaGetSymbolAddress((void**)&delta, g_delta);
    cudaGetSymbolAddress((void**)&y,     g_y);

    // 1. xz = x @ in_proj_w.T  (M=2048, N=4096, K=1024)
    bf16_gemm<4, 4, 0><<<dim3(4096 / 128, 2048 / 128, 1), 512>>>(
        x, in_proj_w, xz, D_MODEL, D_MODEL, 2 * D_INNER, D_MODEL / 16, 0, nullptr);

    // 2. xc = silu(causal_conv(xi) + b)
    conv_silu_kernel<<<(BB * LL * D_INNER + 255) / 256, 256>>>(
        xz, conv_w, conv_b, xc);

    // 3. x_dbl = xc @ x_proj_w.T  (M=2048, N=96, K=2048), split-K=4
    bf16_gemm<2, 3, 0><<<dim3(1, 2048 / 64, KSPLIT), 192>>>(
        xc, x_proj_w, xpart, D_INNER, D_INNER, XPROJ_N,
        D_INNER / KSPLIT / 16, (long)BL * XPROJ_N, nullptr);
    reduce_k<<<(BL * XPROJ_N / 4 + 255) / 256, 256>>>(xpart, xdbl);

    // 4. delta = softplus(dt @ dt_proj_w.T + b)  (M=2048, N=2048, K=64, lda=96)
    bf16_gemm<4, 4, 1><<<dim3(2048 / 128, 2048 / 128, 1), 512>>>(
        xdbl, dt_proj_w, delta, XPROJ_N, DT_RANK, D_INNER, DT_RANK / 16, 0, dt_proj_b);

    // 5. selective scan + D skip + SiLU(z) gating
    scan_kernel<<<(BB * D_INNER * D_STATE) / 256, 256>>>(
        delta, xdbl, xc, xz, A_log, Dv, y);

    // 6. out = y @ out_proj_w.T  (M=2048, N=1024, K=2048)
    bf16_gemm<4, 4, 0><<<dim3(1024 / 128, 2048 / 128, 1), 512>>>(
        y, out_proj, out, D_INNER, D_INNER, D_MODEL, D_INNER / 16, 0, nullptr);
}